// round 5
// baseline (speedup 1.0000x reference)
#include <cuda_runtime.h>
#include <cuda_bf16.h>

// Problem constants
#define BB    16
#define MM    127
#define PP    3
#define KLEN  132
#define NSPAN 126
#define SS    256
#define CDIM  3
#define EPSF  1e-8f

// Scratch (__device__ globals; no allocs allowed)
__device__ float4 g_Nu4[BB][SS];
__device__ float4 g_Nv4[BB][SS];
__device__ int    g_uspan[BB][SS];
__device__ int    g_vspan[BB][SS];

// ---------------------------------------------------------------------------
// Prep: one block per (dir, batch) = 32 blocks, 256 threads.
// Warp-0 shuffle scan for the knot cumsum (5 elems/lane local prefix +
// shfl_up scan of lane sums) -> 3 barriers total. Span via binary search
// (masked-argmin over strictly increasing knots == last index with
// t-K[3+i] > EPS). Basis keeps the reference's exact FP expression order.
// ---------------------------------------------------------------------------
__global__ __launch_bounds__(SS) void prep_kernel(
    const float* __restrict__ knot_u,
    const float* __restrict__ knot_v,
    const float* __restrict__ uu,
    const float* __restrict__ vv)
{
    const int b   = blockIdx.x & 15;
    const int dir = blockIdx.x >> 4;          // 0 = u, 1 = v
    const int tid = threadIdx.x;

    __shared__ float sK[KLEN];

    const float* knots = dir ? knot_v : knot_u;

    if (tid < 32) {
        const int lane = tid;
        float vals[5];
        float run = 0.f;
        #pragma unroll
        for (int k = 0; k < 5; k++) {
            const int idx = lane * 5 + k;
            if (idx < KLEN) {
                float w = knots[b * KLEN + idx];
                run += (w < 0.f) ? 1e-4f : w;
                vals[k] = run;
            }
        }
        // inclusive shuffle scan of per-lane totals
        float tot = run;
        #pragma unroll
        for (int off = 1; off < 32; off <<= 1) {
            float n = __shfl_up_sync(0xFFFFFFFFu, tot, off);
            if (lane >= off) tot += n;
        }
        const float pre = tot - run;          // exclusive prefix
        #pragma unroll
        for (int k = 0; k < 5; k++) {
            const int idx = lane * 5 + k;
            if (idx < KLEN) sK[idx] = vals[k] + pre;
        }
    }
    __syncthreads();

    const float k0  = sK[0];
    const float inv = 1.f / (sK[KLEN - 1] - k0);
    __syncthreads();
    if (tid < KLEN) sK[tid] = (sK[tid] - k0) * inv;
    __syncthreads();

    const int s = tid;
    const float t = (dir ? vv : uu)[s];

    // Binary search: last i in [0, NSPAN) with (t - sK[3+i]) > EPS; -1 -> 0.
    int lo = -1, hi = NSPAN;
    while (hi - lo > 1) {
        const int mid = (lo + hi) >> 1;
        if (t - sK[3 + mid] > EPSF) lo = mid; else hi = mid;
    }
    int idx = (lo < 0) ? 0 : lo;
    int span = idx + PP;
    span = (span < PP) ? PP : (span > MM ? MM : span);

    float Ni[4];
    Ni[0] = 1.f; Ni[1] = 0.f; Ni[2] = 0.f; Ni[3] = 0.f;
    #pragma unroll
    for (int k = 1; k <= PP; k++) {
        float saved = 0.f;
        #pragma unroll
        for (int r = 0; r < 3; r++) {
            if (r >= k) break;
            const float K1 = sK[span + r + 1];
            const float K2 = sK[span + 1 - k + r];
            const float denom = (K1 - t) + (t - K2);       // exact ref order
            const float temp  = (denom == 0.f) ? 1e-4f : Ni[r] / denom;
            Ni[r] = saved + (K1 - t) * temp;
            saved = (t - K2) * temp;
        }
        Ni[k] = saved;
    }

    const float4 packed = make_float4(Ni[0], Ni[1], Ni[2], Ni[3]);
    if (dir == 0) { g_Nu4[b][s] = packed; g_uspan[b][s] = span; }
    else          { g_Nv4[b][s] = packed; g_vspan[b][s] = span; }
}

// ---------------------------------------------------------------------------
// Eval: one 128-thread block per (b, iu).
// Stage 1: threads 0..95 compute the u-contracted row via 4 LDG.128 each,
//          then SCATTER their 4 result floats into a PADDED (x,y,z,0) float4
//          per-column smem layout (4 scalar STS).
// Stage 2: each thread evaluates two points (iv = tid, tid+128) with just
//          4 LDS.128 + 12 FMA per point. Stage-2 operands are loaded before
//          the barrier to hide their latency under stage 1.
// ---------------------------------------------------------------------------
#define EVT 128
__global__ __launch_bounds__(EVT) void eval_kernel(
    const float* __restrict__ ctrl,
    float* __restrict__ out)
{
    const int bid = blockIdx.x;        // 0 .. B*SU-1
    const int b  = bid >> 8;
    const int iu = bid & 255;
    const int tid = threadIdx.x;

    __shared__ float4 sP[128];         // padded u-contracted row: (x,y,z,0) per column

    // Uniform broadcast loads
    const float4 nu = g_Nu4[b][iu];
    const int    us = g_uspan[b][iu];

    // Stage-2 operands: issue early (independent of stage 1)
    const int iv0 = tid, iv1 = tid + EVT;
    const float4 nv0 = g_Nv4[b][iv0];
    const float4 nv1 = g_Nv4[b][iv1];
    const int    vs0 = g_vspan[b][iv0];
    const int    vs1 = g_vspan[b][iv1];

    if (tid < 96) {
        const float4* cb4 = (const float4*)(ctrl + (size_t)(b * 128 + (us - 3)) * 384);
        const float4 r0 = cb4[tid];
        const float4 r1 = cb4[tid + 96];
        const float4 r2 = cb4[tid + 192];
        const float4 r3 = cb4[tid + 288];
        float acc[4];
        acc[0] = nu.x * r0.x + nu.y * r1.x + nu.z * r2.x + nu.w * r3.x;
        acc[1] = nu.x * r0.y + nu.y * r1.y + nu.z * r2.y + nu.w * r3.y;
        acc[2] = nu.x * r0.z + nu.y * r1.z + nu.z * r2.z + nu.w * r3.z;
        acc[3] = nu.x * r0.w + nu.y * r1.w + nu.z * r2.w + nu.w * r3.w;
        // scatter into padded layout: float f = 4*tid+k -> column j=f/3, comp c=f%3
        float* sPf = (float*)sP;
        const int f0 = 4 * tid;
        #pragma unroll
        for (int k = 0; k < 4; k++) {
            const int f = f0 + k;
            const int j = f / 3;
            const int c = f - 3 * j;
            sPf[(j << 2) + c] = acc[k];
        }
    }
    __syncthreads();

    const size_t obase = (size_t)bid * SS;

    {
        const float4* pr = sP + (vs0 - 3);
        const float4 p0 = pr[0], p1 = pr[1], p2 = pr[2], p3 = pr[3];
        const float ax = nv0.x * p0.x + nv0.y * p1.x + nv0.z * p2.x + nv0.w * p3.x;
        const float ay = nv0.x * p0.y + nv0.y * p1.y + nv0.z * p2.y + nv0.w * p3.y;
        const float az = nv0.x * p0.z + nv0.y * p1.z + nv0.z * p2.z + nv0.w * p3.z;
        const size_t o = (obase + iv0) * CDIM;
        out[o] = ax; out[o + 1] = ay; out[o + 2] = az;
    }
    {
        const float4* pr = sP + (vs1 - 3);
        const float4 p0 = pr[0], p1 = pr[1], p2 = pr[2], p3 = pr[3];
        const float ax = nv1.x * p0.x + nv1.y * p1.x + nv1.z * p2.x + nv1.w * p3.x;
        const float ay = nv1.x * p0.y + nv1.y * p1.y + nv1.z * p2.y + nv1.w * p3.y;
        const float az = nv1.x * p0.z + nv1.y * p1.z + nv1.z * p2.z + nv1.w * p3.z;
        const size_t o = (obase + iv1) * CDIM;
        out[o] = ax; out[o + 1] = ay; out[o + 2] = az;
    }
}

// ---------------------------------------------------------------------------
// Inputs (metadata order): ctrl_pts, knot_u, knot_v, u, v. Output: float32.
// ---------------------------------------------------------------------------
extern "C" void kernel_launch(void* const* d_in, const int* in_sizes, int n_in,
                              void* d_out, int out_size)
{
    const float* ctrl   = (const float*)d_in[0];
    const float* knot_u = (const float*)d_in[1];
    const float* knot_v = (const float*)d_in[2];
    const float* uu     = (const float*)d_in[3];
    const float* vv     = (const float*)d_in[4];
    float* out = (float*)d_out;

    prep_kernel<<<2 * BB, SS>>>(knot_u, knot_v, uu, vv);
    eval_kernel<<<BB * SS, EVT>>>(ctrl, out);
}

// round 6
// speedup vs baseline: 1.5038x; 1.5038x over previous
#include <cuda_runtime.h>
#include <cuda_bf16.h>

// Problem constants
#define BB    16
#define MM    127
#define PP    3
#define KLEN  132
#define NSPAN 126
#define SS    256
#define CDIM  3
#define EPSF  1e-8f

// Scratch (__device__ globals; no allocs allowed)
__device__ float4 g_Nu4[BB][SS];
__device__ float4 g_Nv4[BB][SS];
__device__ int    g_uspan[BB][SS];
__device__ int    g_vspan[BB][SS];

// ---------------------------------------------------------------------------
// Prep: one block per (dir, batch) = 32 blocks, 256 threads.
// Warp-0 shuffle scan for the knot cumsum; span via binary search (the
// masked-argmin over strictly increasing knots == last index with
// t-K[3+i] > EPS). Basis keeps the reference's exact FP expression order.
// ---------------------------------------------------------------------------
__global__ __launch_bounds__(SS) void prep_kernel(
    const float* __restrict__ knot_u,
    const float* __restrict__ knot_v,
    const float* __restrict__ uu,
    const float* __restrict__ vv)
{
    const int b   = blockIdx.x & 15;
    const int dir = blockIdx.x >> 4;          // 0 = u, 1 = v
    const int tid = threadIdx.x;

    __shared__ float sK[KLEN];

    const float* knots = dir ? knot_v : knot_u;

    if (tid < 32) {
        const int lane = tid;
        float vals[5];
        float run = 0.f;
        #pragma unroll
        for (int k = 0; k < 5; k++) {
            const int idx = lane * 5 + k;
            if (idx < KLEN) {
                float w = knots[b * KLEN + idx];
                run += (w < 0.f) ? 1e-4f : w;
                vals[k] = run;
            }
        }
        float tot = run;
        #pragma unroll
        for (int off = 1; off < 32; off <<= 1) {
            float n = __shfl_up_sync(0xFFFFFFFFu, tot, off);
            if (lane >= off) tot += n;
        }
        const float pre = tot - run;          // exclusive prefix
        #pragma unroll
        for (int k = 0; k < 5; k++) {
            const int idx = lane * 5 + k;
            if (idx < KLEN) sK[idx] = vals[k] + pre;
        }
    }
    __syncthreads();

    const float k0  = sK[0];
    const float inv = 1.f / (sK[KLEN - 1] - k0);
    __syncthreads();
    if (tid < KLEN) sK[tid] = (sK[tid] - k0) * inv;
    __syncthreads();

    const int s = tid;
    const float t = (dir ? vv : uu)[s];

    int lo = -1, hi = NSPAN;
    while (hi - lo > 1) {
        const int mid = (lo + hi) >> 1;
        if (t - sK[3 + mid] > EPSF) lo = mid; else hi = mid;
    }
    int idx = (lo < 0) ? 0 : lo;
    int span = idx + PP;
    span = (span < PP) ? PP : (span > MM ? MM : span);

    float Ni[4];
    Ni[0] = 1.f; Ni[1] = 0.f; Ni[2] = 0.f; Ni[3] = 0.f;
    #pragma unroll
    for (int k = 1; k <= PP; k++) {
        float saved = 0.f;
        #pragma unroll
        for (int r = 0; r < 3; r++) {
            if (r >= k) break;
            const float K1 = sK[span + r + 1];
            const float K2 = sK[span + 1 - k + r];
            const float denom = (K1 - t) + (t - K2);       // exact ref order
            const float temp  = (denom == 0.f) ? 1e-4f : Ni[r] / denom;
            Ni[r] = saved + (K1 - t) * temp;
            saved = (t - K2) * temp;
        }
        Ni[k] = saved;
    }

    const float4 packed = make_float4(Ni[0], Ni[1], Ni[2], Ni[3]);
    if (dir == 0) { g_Nu4[b][s] = packed; g_uspan[b][s] = span; }
    else          { g_Nv4[b][s] = packed; g_vspan[b][s] = span; }
}

// ---------------------------------------------------------------------------
// Eval: one 128-thread block per (b, group of 4 consecutive iu).
// Software-pipelined: stage-1 LDGs for iu_{g+1} are issued before the barrier
// of iu_g, so their latency hides under stage-2 + STG of iu_g. Double-buffered
// sT keeps one barrier per iteration. Nv/vspan loaded once, reused x4.
// Stage-2 uses the proven scalar-LDS layout (R2) — fewest crossbar wavefronts.
// ---------------------------------------------------------------------------
#define EVT 128
#define GPB 4                               // iu per block
__global__ __launch_bounds__(EVT) void eval_kernel(
    const float* __restrict__ ctrl,
    float* __restrict__ out)
{
    const int bid  = blockIdx.x;            // 0 .. 1023
    const int b    = bid >> 6;
    const int iug  = (bid & 63) * GPB;      // first iu of this group
    const int tid  = threadIdx.x;

    __shared__ float sT[2][128 * CDIM];     // double-buffered u-contracted row

    // Per-block persistent stage-2 operands (reused for all 4 iu)
    const int iv0 = tid, iv1 = tid + EVT;
    const float4 nv0 = g_Nv4[b][iv0];
    const float4 nv1 = g_Nv4[b][iv1];
    const int voff0 = (g_vspan[b][iv0] - 3) * CDIM;
    const int voff1 = (g_vspan[b][iv1] - 3) * CDIM;

    // Per-iu uniform operands
    float4 nu[GPB]; int us[GPB];
    #pragma unroll
    for (int g = 0; g < GPB; g++) {
        nu[g] = g_Nu4[b][iug + g];
        us[g] = g_uspan[b][iug + g];
    }

    const int lt = tid;                     // loader lane (only tid<96 loads)
    float4 r0, r1, r2, r3;

    // Prologue: issue loads for g = 0
    if (lt < 96) {
        const float4* cb4 = (const float4*)(ctrl + (size_t)(b * 128 + (us[0] - 3)) * 384);
        r0 = cb4[lt]; r1 = cb4[lt + 96]; r2 = cb4[lt + 192]; r3 = cb4[lt + 288];
    }

    #pragma unroll
    for (int g = 0; g < GPB; g++) {
        const int p = g & 1;

        // Stage 1: consume in-flight loads, write sT[p]
        if (lt < 96) {
            const float4 q = nu[g];
            float4 acc;
            acc.x = q.x * r0.x + q.y * r1.x + q.z * r2.x + q.w * r3.x;
            acc.y = q.x * r0.y + q.y * r1.y + q.z * r2.y + q.w * r3.y;
            acc.z = q.x * r0.z + q.y * r1.z + q.z * r2.z + q.w * r3.z;
            acc.w = q.x * r0.w + q.y * r1.w + q.z * r2.w + q.w * r3.w;
            ((float4*)sT[p])[lt] = acc;
        }

        // Issue next iteration's loads BEFORE the barrier (latency overlap)
        if (g + 1 < GPB && lt < 96) {
            const float4* cb4 = (const float4*)(ctrl + (size_t)(b * 128 + (us[g + 1] - 3)) * 384);
            r0 = cb4[lt]; r1 = cb4[lt + 96]; r2 = cb4[lt + 192]; r3 = cb4[lt + 288];
        }

        __syncthreads();

        // Stage 2: two points per thread from sT[p] (scalar LDS, conflict-light)
        const float* t0 = sT[p] + voff0;
        const float* t1 = sT[p] + voff1;
        const size_t obase = (((size_t)b * SS + (iug + g)) * SS) * CDIM;
        {
            const float ax = nv0.x * t0[0] + nv0.y * t0[3] + nv0.z * t0[6] + nv0.w * t0[9];
            const float ay = nv0.x * t0[1] + nv0.y * t0[4] + nv0.z * t0[7] + nv0.w * t0[10];
            const float az = nv0.x * t0[2] + nv0.y * t0[5] + nv0.z * t0[8] + nv0.w * t0[11];
            const size_t o = obase + (size_t)iv0 * CDIM;
            out[o] = ax; out[o + 1] = ay; out[o + 2] = az;
        }
        {
            const float ax = nv1.x * t1[0] + nv1.y * t1[3] + nv1.z * t1[6] + nv1.w * t1[9];
            const float ay = nv1.x * t1[1] + nv1.y * t1[4] + nv1.z * t1[7] + nv1.w * t1[10];
            const float az = nv1.x * t1[2] + nv1.y * t1[5] + nv1.z * t1[8] + nv1.w * t1[11];
            const size_t o = obase + (size_t)iv1 * CDIM;
            out[o] = ax; out[o + 1] = ay; out[o + 2] = az;
        }
        // No second barrier: double buffer + next iteration's barrier covers WAR.
    }
}

// ---------------------------------------------------------------------------
// Inputs (metadata order): ctrl_pts, knot_u, knot_v, u, v. Output: float32.
// ---------------------------------------------------------------------------
extern "C" void kernel_launch(void* const* d_in, const int* in_sizes, int n_in,
                              void* d_out, int out_size)
{
    const float* ctrl   = (const float*)d_in[0];
    const float* knot_u = (const float*)d_in[1];
    const float* knot_v = (const float*)d_in[2];
    const float* uu     = (const float*)d_in[3];
    const float* vv     = (const float*)d_in[4];
    float* out = (float*)d_out;

    prep_kernel<<<2 * BB, SS>>>(knot_u, knot_v, uu, vv);
    eval_kernel<<<BB * SS / GPB, EVT>>>(ctrl, out);
}